// round 4
// baseline (speedup 1.0000x reference)
#include <cuda_runtime.h>
#include <cuda_bf16.h>

// Problem constants
#define B_  16
#define C_  4096
#define HD_ 1024   // H*D
#define F_  1024

// GEMM tiling: grid = (NF, NK), block = 256 threads (2 b-halves x 128 f-cols)
#define NF  8
#define TFX 128
#define NK  16
#define TK  64
#define BH  8      // b's per thread (half of B_)

// Split-K partials: distinct slot per (k-chunk, b, f). Plain stores, no atomics.
__device__ float g_part[NK][B_][F_];   // 1 MB scratch

// ---------------------------------------------------------------------------
// Kernel 1: partial GEMM. Attention degenerates (T=1 causal => one-hot at
// rotated position 0) to v_sel[b] = bf16(kv_value[b, start_b]) -- or the
// fresh x@wv+bv row iff idx==0. Block (fx,kx): 256 threads; threads 0..127
// compute b 0..7 for f-tile fx over k-chunk kx, threads 128..255 compute
// b 8..15 for the SAME f/k tile (wo re-read hits L1).
// ---------------------------------------------------------------------------
__global__ void __launch_bounds__(2 * TFX)
gemm_partial_kernel(const float* __restrict__ x,
                    const int*   __restrict__ kv_idx,
                    const float* __restrict__ kv_value,
                    const float* __restrict__ wv,
                    const float* __restrict__ bv,
                    const float* __restrict__ wo)
{
    const int fx   = blockIdx.x;
    const int kx   = blockIdx.y;
    const int tid  = threadIdx.x;
    const int lane = tid & (TFX - 1);       // f within tile
    const int half = tid >> 7;              // 0 -> b[0,8), 1 -> b[8,16)
    const int b0   = half * BH;
    const int k0   = kx * TK;
    const int f    = fx * TFX + lane;

    __shared__ float vs[B_][TK];            // bf16-rounded selected v slice
    __shared__ int   s_start[B_];
    __shared__ int   s_new[B_];

    if (tid < B_) {
        const int idx     = kv_idx[tid];
        const int new_idx = idx + 1;
        const int start   = (new_idx <= C_) ? 0 : (new_idx % C_);
        s_start[tid] = start;
        s_new[tid]   = (start == (idx % C_));   // only when idx == 0
    }
    __syncthreads();

    // Gather vs[b][k]: 1024 elems / 256 threads = 4 independent loads each
    #pragma unroll
    for (int i = tid; i < B_ * TK; i += 2 * TFX) {
        const int b = i / TK, k = i % TK;
        if (!s_new[b]) {
            const float v = __ldg(
                &kv_value[((size_t)b * C_ + s_start[b]) * HD_ + k0 + k]);
            vs[b][k] = __bfloat162float(__float2bfloat16(v));
        }
    }
    // Rare fallback (idx==0): fresh row = x[b] @ wv + bv for this k-slice
    for (int b = 0; b < B_; b++) {
        if (s_new[b] && tid < TK) {
            const int j = k0 + tid;
            float acc = bv[j];
            for (int ff = 0; ff < F_; ff++)
                acc = fmaf(__ldg(&x[b * F_ + ff]),
                           __ldg(&wv[(size_t)ff * HD_ + j]), acc);
            vs[b][tid] = __bfloat162float(__float2bfloat16(acc));
        }
    }
    __syncthreads();

    float acc[BH];
    #pragma unroll
    for (int b = 0; b < BH; b++) acc[b] = 0.0f;

    // Main loop: 4 k's per iter. wo straight from global (coalesced 128B
    // lines per warp; both halves read the same tile -> L1 reuse).
    #pragma unroll
    for (int k4 = 0; k4 < TK; k4 += 4) {
        const float w0 = __ldg(&wo[(size_t)(k0 + k4 + 0) * F_ + f]);
        const float w1 = __ldg(&wo[(size_t)(k0 + k4 + 1) * F_ + f]);
        const float w2 = __ldg(&wo[(size_t)(k0 + k4 + 2) * F_ + f]);
        const float w3 = __ldg(&wo[(size_t)(k0 + k4 + 3) * F_ + f]);
        #pragma unroll
        for (int b = 0; b < BH; b++) {
            const float4 v = *reinterpret_cast<const float4*>(&vs[b0 + b][k4]);
            acc[b] = fmaf(v.x, w0,
                     fmaf(v.y, w1,
                     fmaf(v.z, w2,
                     fmaf(v.w, w3, acc[b]))));
        }
    }

    // Coalesced partial stores to distinct slots (no atomics)
    #pragma unroll
    for (int b = 0; b < BH; b++)
        g_part[kx][b0 + b][f] = acc[b];
}

// ---------------------------------------------------------------------------
// Kernel 2: y[b,f] = bo[f] + sum_kx g_part[kx][b][f].
// 128 blocks x 128 threads; 16 independent coalesced loads per thread.
// ---------------------------------------------------------------------------
__global__ void __launch_bounds__(128)
reduce_kernel(const float* __restrict__ bo, float* __restrict__ y)
{
    const int i = blockIdx.x * 128 + threadIdx.x;   // i = b*F_ + f
    const int f = i & (F_ - 1);
    const int b = i >> 10;

    float s0 = bo[f], s1 = 0.f, s2 = 0.f, s3 = 0.f;
    #pragma unroll
    for (int kx = 0; kx < NK; kx += 4) {
        s0 += g_part[kx + 0][b][f];
        s1 += g_part[kx + 1][b][f];
        s2 += g_part[kx + 2][b][f];
        s3 += g_part[kx + 3][b][f];
    }
    y[i] = (s0 + s1) + (s2 + s3);
}

// ---------------------------------------------------------------------------
// Inputs (metadata order): x, mask, kv_idx, kv_key, kv_value,
//                          wq, bq, wk, bk, wv, bv, wo, bo
// ---------------------------------------------------------------------------
extern "C" void kernel_launch(void* const* d_in, const int* in_sizes, int n_in,
                              void* d_out, int out_size)
{
    const float* x        = (const float*)d_in[0];
    const int*   kv_idx   = (const int*)  d_in[2];
    const float* kv_value = (const float*)d_in[4];
    const float* wv       = (const float*)d_in[9];
    const float* bv       = (const float*)d_in[10];
    const float* wo       = (const float*)d_in[11];
    const float* bo       = (const float*)d_in[12];
    float* y = (float*)d_out;

    gemm_partial_kernel<<<dim3(NF, NK), 2 * TFX>>>(x, kv_idx, kv_value,
                                                   wv, bv, wo);
    reduce_kernel<<<(B_ * F_) / 128, 128>>>(bo, y);
}